// round 3
// baseline (speedup 1.0000x reference)
#include <cuda_runtime.h>
#include <cstdint>

#define B_  4
#define S_  2048
#define F_  512
#define E_  512
#define H_  8
#define DH_ 64
#define ROWS_ (B_ * S_)

// Scratch for projected Q/K/V in [B,H,S,DH] layout (16 MB each).
__device__ float g_Q[B_ * H_ * S_ * DH_];
__device__ float g_K[B_ * H_ * S_ * DH_];
__device__ float g_V[B_ * H_ * S_ * DH_];

__device__ __forceinline__ uint32_t f2tf32(float f) {
    uint32_t u;
    asm("cvt.rna.tf32.f32 %0, %1;" : "=r"(u) : "f"(f));
    return u;
}

__device__ __forceinline__ float f2tf32f(float f) {
    return __uint_as_float(f2tf32(f));
}

__device__ __forceinline__ void mma_tf32(float c[4],
                                         uint32_t a0, uint32_t a1, uint32_t a2, uint32_t a3,
                                         uint32_t b0, uint32_t b1) {
    asm volatile(
        "mma.sync.aligned.m16n8k8.row.col.f32.tf32.tf32.f32 "
        "{%0,%1,%2,%3},{%4,%5,%6,%7},{%8,%9},{%0,%1,%2,%3};\n"
        : "+f"(c[0]), "+f"(c[1]), "+f"(c[2]), "+f"(c[3])
        : "r"(a0), "r"(a1), "r"(a2), "r"(a3), "r"(b0), "r"(b1));
}

// ---------------------------------------------------------------------------
// Kernel 1: fused QKV projection.
// out[z] = x @ W[z] + b[z] (+ etype for z==0), written in [B,H,S,DH] layout.
// Tile: BM=64, BN=64, BK=32. 4 warps, each computes 16(m) x 64(n).
// ---------------------------------------------------------------------------
__global__ __launch_bounds__(128) void qkv_kernel(
    const float* __restrict__ x, const float* __restrict__ etype,
    const float* __restrict__ Wq, const float* __restrict__ bq,
    const float* __restrict__ Wk, const float* __restrict__ bk,
    const float* __restrict__ Wv, const float* __restrict__ bv)
{
    const int z = blockIdx.z;
    const float* W    = (z == 0) ? Wq : (z == 1) ? Wk : Wv;
    const float* bias = (z == 0) ? bq : (z == 1) ? bk : bv;
    float* out        = (z == 0) ? g_Q : (z == 1) ? g_K : g_V;

    __shared__ float As[64][36];   // x tile   [BM][BK]  (+pad)
    __shared__ float Bs[32][68];   // W tile   [BK][BN]  (+pad)

    const int tid  = threadIdx.x;
    const int lane = tid & 31;
    const int warp = tid >> 5;
    const int g    = lane >> 2;
    const int tg   = lane & 3;
    const int wm   = warp * 16;
    const int row0 = blockIdx.x * 64;
    const int col0 = blockIdx.y * 64;

    float acc[8][4];
#pragma unroll
    for (int nt = 0; nt < 8; nt++)
#pragma unroll
        for (int i = 0; i < 4; i++) acc[nt][i] = 0.f;

    for (int k0 = 0; k0 < F_; k0 += 32) {
#pragma unroll
        for (int i = 0; i < 4; i++) {              // A: 64 x 32 floats
            int u = tid + i * 128;
            int r = u >> 3, c = (u & 7) * 4;
            float4 v = *(const float4*)&x[(size_t)(row0 + r) * F_ + k0 + c];
            v.x = f2tf32f(v.x); v.y = f2tf32f(v.y);
            v.z = f2tf32f(v.z); v.w = f2tf32f(v.w);
            *(float4*)&As[r][c] = v;
        }
#pragma unroll
        for (int i = 0; i < 4; i++) {              // B: 32 x 64 floats
            int u = tid + i * 128;
            int r = u >> 4, c = (u & 15) * 4;
            float4 v = *(const float4*)&W[(size_t)(k0 + r) * E_ + col0 + c];
            v.x = f2tf32f(v.x); v.y = f2tf32f(v.y);
            v.z = f2tf32f(v.z); v.w = f2tf32f(v.w);
            *(float4*)&Bs[r][c] = v;
        }
        __syncthreads();
#pragma unroll
        for (int ks = 0; ks < 4; ks++) {
            uint32_t a0 = __float_as_uint(As[wm + g    ][ks * 8 + tg    ]);
            uint32_t a1 = __float_as_uint(As[wm + g + 8][ks * 8 + tg    ]);
            uint32_t a2 = __float_as_uint(As[wm + g    ][ks * 8 + tg + 4]);
            uint32_t a3 = __float_as_uint(As[wm + g + 8][ks * 8 + tg + 4]);
#pragma unroll
            for (int nt = 0; nt < 8; nt++) {
                uint32_t b0 = __float_as_uint(Bs[ks * 8 + tg    ][nt * 8 + g]);
                uint32_t b1 = __float_as_uint(Bs[ks * 8 + tg + 4][nt * 8 + g]);
                mma_tf32(acc[nt], a0, a1, a2, a3, b0, b1);
            }
        }
        __syncthreads();
    }

    // Epilogue: bias (+etype for Q), scatter to [B,H,S,DH].
    const int rg0 = row0 + wm + g;
    const int rg1 = rg0 + 8;
#pragma unroll
    for (int nt = 0; nt < 8; nt++) {
        int col = col0 + nt * 8 + tg * 2;
        float bv0 = bias[col], bv1 = bias[col + 1];
        float v00 = acc[nt][0] + bv0, v01 = acc[nt][1] + bv1;
        float v10 = acc[nt][2] + bv0, v11 = acc[nt][3] + bv1;
        if (z == 0) {
            float2 e0 = *(const float2*)&etype[(size_t)rg0 * E_ + col];
            float2 e1 = *(const float2*)&etype[(size_t)rg1 * E_ + col];
            v00 += e0.x; v01 += e0.y;
            v10 += e1.x; v11 += e1.y;
        }
        int hh = col >> 6, d = col & 63;
        int b0i = rg0 >> 11, s0i = rg0 & (S_ - 1);
        int b1i = rg1 >> 11, s1i = rg1 & (S_ - 1);
        *(float2*)&out[(((size_t)b0i * H_ + hh) * S_ + s0i) * DH_ + d] = make_float2(v00, v01);
        *(float2*)&out[(((size_t)b1i * H_ + hh) * S_ + s1i) * DH_ + d] = make_float2(v10, v11);
    }
}

// ---------------------------------------------------------------------------
// Kernel 2: flash attention. One block per (b, h, 64-query tile).
// 4 warps x 16 query rows. Q fragments in registers; K tile and P tile
// share S1 smem (fenced by __syncthreads); V in S2.
// ---------------------------------------------------------------------------
__global__ __launch_bounds__(128) void attn_kernel(
    const int* __restrict__ mask, float* __restrict__ out)
{
    __shared__ float S1[64][68];   // Q stage -> K tile -> P tile
    __shared__ float S2[64][68];   // V tile
    __shared__ float kmf[64];      // key mask as float

    const int tid  = threadIdx.x;
    const int lane = tid & 31;
    const int warp = tid >> 5;
    const int g    = lane >> 2;
    const int tg   = lane & 3;
    const int wm   = warp * 16;
    const int q0   = blockIdx.x * 64;
    const int bh   = blockIdx.y;
    const int b    = bh >> 3, h = bh & 7;

    const float* Qp = g_Q + (size_t)bh * S_ * DH_;
    const float* Kp = g_K + (size_t)bh * S_ * DH_;
    const float* Vp = g_V + (size_t)bh * S_ * DH_;
    const int*   mp = mask + b * S_;

    // Stage Q (tf32) then move fragments to registers.
#pragma unroll
    for (int i = 0; i < 8; i++) {
        int u = tid + i * 128;
        int r = u >> 4, c = (u & 15) * 4;
        float4 v = *(const float4*)&Qp[(size_t)(q0 + r) * DH_ + c];
        v.x = f2tf32f(v.x); v.y = f2tf32f(v.y);
        v.z = f2tf32f(v.z); v.w = f2tf32f(v.w);
        *(float4*)&S1[r][c] = v;
    }
    __syncthreads();
    uint32_t qf[8][4];
#pragma unroll
    for (int ks = 0; ks < 8; ks++) {
        qf[ks][0] = __float_as_uint(S1[wm + g    ][ks * 8 + tg    ]);
        qf[ks][1] = __float_as_uint(S1[wm + g + 8][ks * 8 + tg    ]);
        qf[ks][2] = __float_as_uint(S1[wm + g    ][ks * 8 + tg + 4]);
        qf[ks][3] = __float_as_uint(S1[wm + g + 8][ks * 8 + tg + 4]);
    }
    __syncthreads();

    float m0 = -1e30f, m1 = -1e30f, l0 = 0.f, l1 = 0.f;
    float O[8][4];
#pragma unroll
    for (int nt = 0; nt < 8; nt++)
#pragma unroll
        for (int i = 0; i < 4; i++) O[nt][i] = 0.f;

    for (int kt = 0; kt < S_ / 64; kt++) {
        const int k0 = kt * 64;
#pragma unroll
        for (int i = 0; i < 8; i++) {
            int u = tid + i * 128;
            int r = u >> 4, c = (u & 15) * 4;
            float4 kv = *(const float4*)&Kp[(size_t)(k0 + r) * DH_ + c];
            kv.x = f2tf32f(kv.x); kv.y = f2tf32f(kv.y);
            kv.z = f2tf32f(kv.z); kv.w = f2tf32f(kv.w);
            *(float4*)&S1[r][c] = kv;
            float4 vv = *(const float4*)&Vp[(size_t)(k0 + r) * DH_ + c];
            vv.x = f2tf32f(vv.x); vv.y = f2tf32f(vv.y);
            vv.z = f2tf32f(vv.z); vv.w = f2tf32f(vv.w);
            *(float4*)&S2[r][c] = vv;
        }
        if (tid < 64) kmf[tid] = (mp[k0 + tid] != 0) ? 1.f : 0.f;
        __syncthreads();

        // S = Q @ K^T   (m=query, n=key, k=dh)
        float sc[8][4];
#pragma unroll
        for (int nt = 0; nt < 8; nt++)
#pragma unroll
            for (int i = 0; i < 4; i++) sc[nt][i] = 0.f;
#pragma unroll
        for (int ks = 0; ks < 8; ks++) {
#pragma unroll
            for (int nt = 0; nt < 8; nt++) {
                uint32_t b0 = __float_as_uint(S1[nt * 8 + g][ks * 8 + tg    ]);
                uint32_t b1 = __float_as_uint(S1[nt * 8 + g][ks * 8 + tg + 4]);
                mma_tf32(sc[nt], qf[ks][0], qf[ks][1], qf[ks][2], qf[ks][3], b0, b1);
            }
        }

        // Scale + key mask (exactly as reference: masked score == -1e10).
        float rmax0 = -1e30f, rmax1 = -1e30f;
#pragma unroll
        for (int nt = 0; nt < 8; nt++) {
            int c = nt * 8 + tg * 2;
            float km0 = kmf[c], km1 = kmf[c + 1];
            sc[nt][0] = (km0 != 0.f) ? sc[nt][0] * 0.125f : -1e10f;
            sc[nt][1] = (km1 != 0.f) ? sc[nt][1] * 0.125f : -1e10f;
            sc[nt][2] = (km0 != 0.f) ? sc[nt][2] * 0.125f : -1e10f;
            sc[nt][3] = (km1 != 0.f) ? sc[nt][3] * 0.125f : -1e10f;
            rmax0 = fmaxf(rmax0, fmaxf(sc[nt][0], sc[nt][1]));
            rmax1 = fmaxf(rmax1, fmaxf(sc[nt][2], sc[nt][3]));
        }
        rmax0 = fmaxf(rmax0, __shfl_xor_sync(0xffffffffu, rmax0, 1));
        rmax0 = fmaxf(rmax0, __shfl_xor_sync(0xffffffffu, rmax0, 2));
        rmax1 = fmaxf(rmax1, __shfl_xor_sync(0xffffffffu, rmax1, 1));
        rmax1 = fmaxf(rmax1, __shfl_xor_sync(0xffffffffu, rmax1, 2));

        float mn0 = fmaxf(m0, rmax0), mn1 = fmaxf(m1, rmax1);
        float al0 = __expf(m0 - mn0), al1 = __expf(m1 - mn1);

        __syncthreads();   // all warps done reading K tile before P overwrite

        float ls0 = 0.f, ls1 = 0.f;
#pragma unroll
        for (int nt = 0; nt < 8; nt++) {
            int c = nt * 8 + tg * 2;
            float p0 = __expf(sc[nt][0] - mn0);
            float p1 = __expf(sc[nt][1] - mn0);
            float p2 = __expf(sc[nt][2] - mn1);
            float p3 = __expf(sc[nt][3] - mn1);
            ls0 += p0 + p1;
            ls1 += p2 + p3;
            S1[wm + g    ][c]     = f2tf32f(p0);
            S1[wm + g    ][c + 1] = f2tf32f(p1);
            S1[wm + g + 8][c]     = f2tf32f(p2);
            S1[wm + g + 8][c + 1] = f2tf32f(p3);
        }
        ls0 += __shfl_xor_sync(0xffffffffu, ls0, 1);
        ls0 += __shfl_xor_sync(0xffffffffu, ls0, 2);
        ls1 += __shfl_xor_sync(0xffffffffu, ls1, 1);
        ls1 += __shfl_xor_sync(0xffffffffu, ls1, 2);

        l0 = l0 * al0 + ls0;
        l1 = l1 * al1 + ls1;
        m0 = mn0; m1 = mn1;
#pragma unroll
        for (int nt = 0; nt < 8; nt++) {
            O[nt][0] *= al0; O[nt][1] *= al0;
            O[nt][2] *= al1; O[nt][3] *= al1;
        }
        __syncwarp();

        // O += P @ V   (m=query, n=dh, k=key). P rows are warp-private.
#pragma unroll
        for (int k2 = 0; k2 < 8; k2++) {
            uint32_t a0 = __float_as_uint(S1[wm + g    ][k2 * 8 + tg    ]);
            uint32_t a1 = __float_as_uint(S1[wm + g + 8][k2 * 8 + tg    ]);
            uint32_t a2 = __float_as_uint(S1[wm + g    ][k2 * 8 + tg + 4]);
            uint32_t a3 = __float_as_uint(S1[wm + g + 8][k2 * 8 + tg + 4]);
#pragma unroll
            for (int nt = 0; nt < 8; nt++) {
                uint32_t b0 = __float_as_uint(S2[k2 * 8 + tg    ][nt * 8 + g]);
                uint32_t b1 = __float_as_uint(S2[k2 * 8 + tg + 4][nt * 8 + g]);
                mma_tf32(O[nt], a0, a1, a2, a3, b0, b1);
            }
        }
        __syncthreads();   // before next tile's loads overwrite S1/S2
    }

    // Epilogue: normalize, query mask, write [B,S,E].
    const int r0 = q0 + wm + g;
    const int r1 = r0 + 8;
    float inv0 = (mp[r0] != 0) ? 1.f / l0 : 0.f;
    float inv1 = (mp[r1] != 0) ? 1.f / l1 : 0.f;
    float* o0 = out + ((size_t)(b * S_ + r0) * E_) + h * DH_;
    float* o1 = out + ((size_t)(b * S_ + r1) * E_) + h * DH_;
#pragma unroll
    for (int nt = 0; nt < 8; nt++) {
        int c = nt * 8 + tg * 2;
        *(float2*)&o0[c] = make_float2(O[nt][0] * inv0, O[nt][1] * inv0);
        *(float2*)&o1[c] = make_float2(O[nt][2] * inv1, O[nt][3] * inv1);
    }
}

extern "C" void kernel_launch(void* const* d_in, const int* in_sizes, int n_in,
                              void* d_out, int out_size) {
    const float* x     = (const float*)d_in[0];
    const float* etype = (const float*)d_in[1];
    const int*   mask  = (const int*)d_in[2];
    const float* Wq    = (const float*)d_in[3];
    const float* bq    = (const float*)d_in[4];
    const float* Wk    = (const float*)d_in[5];
    const float* bk    = (const float*)d_in[6];
    const float* Wv    = (const float*)d_in[7];
    const float* bv    = (const float*)d_in[8];
    float* out = (float*)d_out;

    dim3 g1(ROWS_ / 64, E_ / 64, 3);
    qkv_kernel<<<g1, 128>>>(x, etype, Wq, bq, Wk, bk, Wv, bv);

    dim3 g2(S_ / 64, B_ * H_);
    attn_kernel<<<g2, 128>>>(mask, out);
}